// round 14
// baseline (speedup 1.0000x reference)
#include <cuda_runtime.h>
#include <cuda_fp16.h>

#define MAXN 50176
#define SLOT 128
#define LOG2E 1.4426950408889634f

// Scratch (__device__ globals; no allocation allowed)
__device__ __align__(256) __half2 g_h2h[MAXN * 32];  // layer-2 features fp16 packed
// per-layer factorized attention tables: a = src side (s, P=2^s, p=2^0.2s, payload), b = dst side (d, Q, q, 0)
__device__ __align__(16) float4 g_a1[MAXN], g_b1[MAXN];   // payload = x
__device__ __align__(16) float4 g_a2[MAXN], g_b2[MAXN];
__device__ __align__(16) float4 g_a3[MAXN], g_b3[MAXN];   // payload = h3
__device__ int g_cursor[MAXN];       // INVARIANT: zero at entry (zero-init at load; gat_out resets)
__device__ int g_csr[MAXN * SLOT];   // fixed-stride CSR
// piecewise-linear table for h2(z) = A_m * z + C_m, 65 segments x 64 features
__device__ __align__(16) float g_tabA[65 * 64];
__device__ __align__(16) float g_tabC[65 * 64];
__device__ float g_knee[64];

// factorized edge weight: exp2(leaky(s+d)) with a=(s,P,p,·), b=(d,Q,q,·); all logits pre-scaled by log2e
__device__ __forceinline__ float edge_w(const float4& a, const float4& b) {
    float t = a.x + b.x;
    float pa = (t > 0.f) ? a.y : a.z;
    float pb = (t > 0.f) ? b.y : b.z;
    return pa * pb;
}

// ======= K1: node prep (factorized layer-1 tables) + CSR scatter + (block 0) PWL table build =======
__global__ void prep_scatter(const float* __restrict__ x, const float* __restrict__ W1,
                             const float* __restrict__ as1, const float* __restrict__ ad1,
                             const float* __restrict__ b1, const float* __restrict__ W2,
                             const int* __restrict__ src, const int* __restrict__ dst,
                             int N, int E) {
    __shared__ float cs_sh, cd_sh;
    int base = blockIdx.x * blockDim.x;
    if (base < N && threadIdx.x == 0) {
        float cs = 0.f, cd = 0.f;
#pragma unroll
        for (int j = 0; j < 64; j++) { cs += W1[j] * as1[j]; cd += W1[j] * ad1[j]; }
        cs_sh = cs * LOG2E; cd_sh = cd * LOG2E;
    }
    if (base < N) __syncthreads();

    // ---- block 0: build the piecewise-linear (A,C) table ----
    if (blockIdx.x == 0) {
        __shared__ float rk[64], rw[64], rb[64];
        __shared__ float sk[64], sw[64], sb[64];
        __shared__ int sidx[64];
        int t = threadIdx.x;
        if (t < 64) {
            float w = W1[t], b = b1[t];
            float knee = (w != 0.f) ? (-b / w) : __int_as_float(0x7f800000);
            rk[t] = knee; rw[t] = w; rb[t] = b;
        }
        __syncthreads();
        if (t < 64) {
            float knee = rk[t];
            int rank = 0;
            for (int j = 0; j < 64; j++)
                rank += (rk[j] < knee) || (rk[j] == knee && j < t);
            float w = rw[t], b = rb[t];
            float sgn = (w > 0.f) ? 1.f : ((w < 0.f) ? -1.f : 0.f);
            sk[rank] = knee; sw[rank] = sgn * w; sb[rank] = sgn * b; sidx[rank] = t;
        }
        __syncthreads();
        if (t < 64) {
            g_knee[t] = sk[t];
            float A = 0.f, C = 0.f;
            for (int j = 0; j < 64; j++) {
                float w = rw[j], b = rb[j];
                bool act = (w < 0.f) || (w == 0.f && b > 0.f);
                if (act) {
                    float w2v = W2[j * 64 + t];
                    A += w * w2v; C += b * w2v;
                }
            }
            g_tabA[t] = A; g_tabC[t] = C;
            for (int m = 1; m <= 64; m++) {
                int j = sidx[m - 1];
                float w2v = W2[j * 64 + t];
                A += sw[m - 1] * w2v; C += sb[m - 1] * w2v;
                g_tabA[m * 64 + t] = A; g_tabC[m * 64 + t] = C;
            }
        }
    }

    // ---- edge work: 4 edges/thread, cursor-ATOMG CSR scatter (R12 structure) ----
    int t = base + threadIdx.x;
    int e0 = t * 4;
    if (e0 + 3 < E) {
        int4 s4 = ((const int4*)src)[t];
        int4 d4 = ((const int4*)dst)[t];
        int r0 = atomicAdd(&g_cursor[d4.x], 1);
        int r1 = atomicAdd(&g_cursor[d4.y], 1);
        int r2 = atomicAdd(&g_cursor[d4.z], 1);
        int r3 = atomicAdd(&g_cursor[d4.w], 1);
        g_csr[d4.x * SLOT + r0] = s4.x;
        g_csr[d4.y * SLOT + r1] = s4.y;
        g_csr[d4.z * SLOT + r2] = s4.z;
        g_csr[d4.w * SLOT + r3] = s4.w;
    } else if (e0 < E) {
        for (int e = e0; e < E; e++) {
            int d = dst[e];
            int r = atomicAdd(&g_cursor[d], 1);
            g_csr[d * SLOT + r] = src[e];
        }
    }
    if (t < N) {
        float xv = x[t];
        float s1 = xv * cs_sh;
        float d1 = xv * cd_sh;
        g_a1[t] = make_float4(s1, exp2f(s1), exp2f(0.2f * s1), xv);
        g_b1[t] = make_float4(d1, exp2f(d1), exp2f(0.2f * d1), 0.f);
    }
}

// ======= K2: layer-1 scalar GAT (factorized, no MUFU per edge) + PWL layer-2 transform =======
__global__ void gat_l1_fused(const float* __restrict__ as2, const float* __restrict__ ad2, int N) {
    int node = (blockIdx.x * blockDim.x + threadIdx.x) >> 5;
    int lane = threadIdx.x & 31;
    if (node >= N) return;
    int off = node * SLOT;
    int deg = g_cursor[node];
    float4 bn = g_b1[node];
    float4 an = g_a1[node];

    float dsum = 0.f, zacc = 0.f;
    for (int j = lane; j < deg; j += 32) {
        int sv = g_csr[off + j];
        float4 tv = g_a1[sv];
        float ex = edge_w(tv, bn);
        dsum += ex;
        zacc += ex * tv.w;
    }
#pragma unroll
    for (int o = 16; o; o >>= 1) {
        dsum += __shfl_xor_sync(0xffffffffu, dsum, o);
        zacc += __shfl_xor_sync(0xffffffffu, zacc, o);
    }
    float exs = edge_w(an, bn);
    float z = (zacc + exs * an.w) / (dsum + exs);

    // PWL segment m = #knees < z (search range [0,64])
    int m = 0;
#pragma unroll
    for (int s = 64; s; s >>= 1) {
        int t = m + s;
        if (t <= 64 && g_knee[t - 1] < z) m = t;
    }
    float2 A = ((const float2*)g_tabA)[m * 32 + lane];
    float2 C = ((const float2*)g_tabC)[m * 32 + lane];
    float o0 = A.x * z + C.x;
    float o1 = A.y * z + C.y;

    g_h2h[node * 32 + lane] = __floats2half2_rn(o0, o1);
    float2 a_s = ((const float2*)as2)[lane];
    float2 a_d = ((const float2*)ad2)[lane];
    float ps = o0 * a_s.x + o1 * a_s.y;
    float pd = o0 * a_d.x + o1 * a_d.y;
#pragma unroll
    for (int o = 16; o; o >>= 1) {
        ps += __shfl_down_sync(0xffffffffu, ps, o);
        pd += __shfl_down_sync(0xffffffffu, pd, o);
    }
    if (lane == 0) {
        float s2 = ps * LOG2E;
        float d2 = pd * LOG2E;
        g_a2[node] = make_float4(s2, exp2f(s2), exp2f(0.2f * s2), 0.f);
        g_b2[node] = make_float4(d2, exp2f(d2), exp2f(0.2f * d2), 0.f);
    }
}

// ======= K3: layer-2 wide GAT (fp16 gather, factorized weights) + layer-3 projection =======
__global__ void gat_l2(const float* __restrict__ b2, const float* __restrict__ W3,
                       const float* __restrict__ as3, const float* __restrict__ ad3, int N) {
    int node = (blockIdx.x * blockDim.x + threadIdx.x) >> 5;
    int lane = threadIdx.x & 31;
    if (node >= N) return;
    int off = node * SLOT;
    int deg = g_cursor[node];
    float4 bn = g_b2[node];
    float4 an = g_a2[node];

    float exs = edge_w(an, bn);
    float2 hself = __half22float2(g_h2h[node * 32 + lane]);
    float a0 = exs * hself.x;
    float a1 = exs * hself.y;
    float dsum = 0.f;
    for (int r = 0; r < deg; r += 32) {
        int j = r + lane;
        int sv = 0;
        float exv = 0.f;
        if (j < deg) {
            sv = g_csr[off + j];
            float4 tv = g_a2[sv];
            exv = edge_w(tv, bn);
        }
        dsum += exv;
        int cnt = min(32, deg - r);
        if (cnt == 32) {
#pragma unroll 8
            for (int k = 0; k < 32; k++) {
                int sj = __shfl_sync(0xffffffffu, sv, k);
                float exj = __shfl_sync(0xffffffffu, exv, k);
                float2 hv = __half22float2(g_h2h[sj * 32 + lane]);
                a0 += exj * hv.x;
                a1 += exj * hv.y;
            }
        } else {
            for (int k = 0; k < cnt; k++) {
                int sj = __shfl_sync(0xffffffffu, sv, k);
                float exj = __shfl_sync(0xffffffffu, exv, k);
                float2 hv = __half22float2(g_h2h[sj * 32 + lane]);
                a0 += exj * hv.x;
                a1 += exj * hv.y;
            }
        }
    }
#pragma unroll
    for (int o = 16; o; o >>= 1) dsum += __shfl_xor_sync(0xffffffffu, dsum, o);
    float inv = 1.f / (exs + dsum);
    float2 bb = ((const float2*)b2)[lane];
    float2 w3 = ((const float2*)W3)[lane];
    float x30 = fmaxf(a0 * inv + bb.x, 0.f);
    float x31 = fmaxf(a1 * inv + bb.y, 0.f);
    float p = x30 * w3.x + x31 * w3.y;
#pragma unroll
    for (int o = 16; o; o >>= 1) p += __shfl_down_sync(0xffffffffu, p, o);
    if (lane == 0) {
        float s3 = p * as3[0] * LOG2E;
        float d3 = p * ad3[0] * LOG2E;
        g_a3[node] = make_float4(s3, exp2f(s3), exp2f(0.2f * s3), p);
        g_b3[node] = make_float4(d3, exp2f(d3), exp2f(0.2f * d3), 0.f);
    }
}

// ======= K4: layer-3 scalar GAT (factorized) -> output; resets cursor invariant =======
__global__ void gat_out(const float* __restrict__ b3, float* __restrict__ out, int N) {
    int node = (blockIdx.x * blockDim.x + threadIdx.x) >> 5;
    int lane = threadIdx.x & 31;
    if (node >= N) return;
    int off = node * SLOT;
    int deg = g_cursor[node];
    float4 bn = g_b3[node];
    float4 an = g_a3[node];

    float dsum = 0.f, acc = 0.f;
    for (int j = lane; j < deg; j += 32) {
        int sv = g_csr[off + j];
        float4 tv = g_a3[sv];
        float ex = edge_w(tv, bn);
        dsum += ex;
        acc += ex * tv.w;
    }
#pragma unroll
    for (int o = 16; o; o >>= 1) {
        dsum += __shfl_xor_sync(0xffffffffu, dsum, o);
        acc += __shfl_xor_sync(0xffffffffu, acc, o);
    }
    if (lane == 0) {
        float exs = edge_w(an, bn);
        out[node] = (acc + exs * an.w) / (dsum + exs) + b3[0];
        g_cursor[node] = 0;   // restore invariant for next call
    }
}

extern "C" void kernel_launch(void* const* d_in, const int* in_sizes, int n_in,
                              void* d_out, int out_size) {
    const float* x   = (const float*)d_in[0];
    const int*   ei  = (const int*)d_in[1];
    const float* W1  = (const float*)d_in[3];
    const float* as1 = (const float*)d_in[4];
    const float* ad1 = (const float*)d_in[5];
    const float* b1  = (const float*)d_in[6];
    const float* W2  = (const float*)d_in[7];
    const float* as2 = (const float*)d_in[8];
    const float* ad2 = (const float*)d_in[9];
    const float* b2  = (const float*)d_in[10];
    const float* W3  = (const float*)d_in[11];
    const float* as3 = (const float*)d_in[12];
    const float* ad3 = (const float*)d_in[13];
    const float* b3  = (const float*)d_in[14];

    int N = in_sizes[0];
    int E = in_sizes[1] / 2;
    const int* src = ei;
    const int* dst = ei + E;

    const int TB = 256;
    int gN32 = (N * 32 + TB - 1) / TB;
    int e4   = (E + 3) / 4;
    int gPS  = (((e4 > N) ? e4 : N) + TB - 1) / TB;

    prep_scatter<<<gPS, TB>>>(x, W1, as1, ad1, b1, W2, src, dst, N, E);
    gat_l1_fused<<<gN32, TB>>>(as2, ad2, N);
    gat_l2<<<gN32, TB>>>(b2, W3, as3, ad3, N);
    gat_out<<<gN32, TB>>>(b3, (float*)d_out, N);
}

// round 15
// speedup vs baseline: 1.0923x; 1.0923x over previous
#include <cuda_runtime.h>
#include <cuda_fp16.h>

#define MAXN 50176
#define SLOT 128
#define LOG2E 1.4426950408889634f

// Scratch (__device__ globals; no allocation allowed)
__device__ __align__(256) __half2 g_h2h[MAXN * 32];  // layer-2 features fp16 packed
__device__ __align__(16) float2 g_sx1[MAXN];         // packed (s1*log2e, x)
__device__ __align__(16) float2 g_sh3[MAXN];         // packed (s3*log2e, h3)
__device__ float g_d1[MAXN];                         // *log2e
__device__ float g_s2[MAXN], g_d2[MAXN];             // *log2e
__device__ float g_d3[MAXN];                         // *log2e
__device__ int g_cursor[MAXN];       // INVARIANT: zero at entry (zero-init at load; gat_out resets)
__device__ int g_csr[MAXN * SLOT];   // fixed-stride CSR
// piecewise-linear table for h2(z) = A_m * z + C_m, 65 segments x 64 features
__device__ __align__(16) float g_tabA[65 * 64];
__device__ __align__(16) float g_tabC[65 * 64];
__device__ float g_knee[64];

__device__ __forceinline__ float leaky(float v) { return v > 0.f ? v : 0.2f * v; }

// ======= K1: node prep (rank-1 layer-1 scalars) + CSR scatter + (block 0) PWL table build =======
__global__ void prep_scatter(const float* __restrict__ x, const float* __restrict__ W1,
                             const float* __restrict__ as1, const float* __restrict__ ad1,
                             const float* __restrict__ b1, const float* __restrict__ W2,
                             const int* __restrict__ src, const int* __restrict__ dst,
                             int N, int E) {
    __shared__ float cs_sh, cd_sh;
    int base = blockIdx.x * blockDim.x;
    if (base < N && threadIdx.x == 0) {
        float cs = 0.f, cd = 0.f;
#pragma unroll
        for (int j = 0; j < 64; j++) { cs += W1[j] * as1[j]; cd += W1[j] * ad1[j]; }
        cs_sh = cs * LOG2E; cd_sh = cd * LOG2E;
    }
    if (base < N) __syncthreads();

    // ---- block 0: build the piecewise-linear (A,C) table ----
    if (blockIdx.x == 0) {
        __shared__ float rk[64], rw[64], rb[64];
        __shared__ float sk[64], sw[64], sb[64];
        __shared__ int sidx[64];
        int t = threadIdx.x;
        if (t < 64) {
            float w = W1[t], b = b1[t];
            float knee = (w != 0.f) ? (-b / w) : __int_as_float(0x7f800000);
            rk[t] = knee; rw[t] = w; rb[t] = b;
        }
        __syncthreads();
        if (t < 64) {
            float knee = rk[t];
            int rank = 0;
            for (int j = 0; j < 64; j++)
                rank += (rk[j] < knee) || (rk[j] == knee && j < t);
            float w = rw[t], b = rb[t];
            float sgn = (w > 0.f) ? 1.f : ((w < 0.f) ? -1.f : 0.f);
            sk[rank] = knee; sw[rank] = sgn * w; sb[rank] = sgn * b; sidx[rank] = t;
        }
        __syncthreads();
        if (t < 64) {
            g_knee[t] = sk[t];
            float A = 0.f, C = 0.f;
            for (int j = 0; j < 64; j++) {
                float w = rw[j], b = rb[j];
                bool act = (w < 0.f) || (w == 0.f && b > 0.f);
                if (act) {
                    float w2v = W2[j * 64 + t];
                    A += w * w2v; C += b * w2v;
                }
            }
            g_tabA[t] = A; g_tabC[t] = C;
            for (int m = 1; m <= 64; m++) {
                int j = sidx[m - 1];
                float w2v = W2[j * 64 + t];
                A += sw[m - 1] * w2v; C += sb[m - 1] * w2v;
                g_tabA[m * 64 + t] = A; g_tabC[m * 64 + t] = C;
            }
        }
    }

    // ---- edge work: 4 edges/thread, cursor-ATOMG CSR scatter (R12 structure) ----
    int t = base + threadIdx.x;
    int e0 = t * 4;
    if (e0 + 3 < E) {
        int4 s4 = ((const int4*)src)[t];
        int4 d4 = ((const int4*)dst)[t];
        int r0 = atomicAdd(&g_cursor[d4.x], 1);
        int r1 = atomicAdd(&g_cursor[d4.y], 1);
        int r2 = atomicAdd(&g_cursor[d4.z], 1);
        int r3 = atomicAdd(&g_cursor[d4.w], 1);
        g_csr[d4.x * SLOT + r0] = s4.x;
        g_csr[d4.y * SLOT + r1] = s4.y;
        g_csr[d4.z * SLOT + r2] = s4.z;
        g_csr[d4.w * SLOT + r3] = s4.w;
    } else if (e0 < E) {
        for (int e = e0; e < E; e++) {
            int d = dst[e];
            int r = atomicAdd(&g_cursor[d], 1);
            g_csr[d * SLOT + r] = src[e];
        }
    }
    if (t < N) {
        float xv = x[t];
        g_sx1[t] = make_float2(xv * cs_sh, xv);
        g_d1[t] = xv * cd_sh;
    }
}

// ======= K2: layer-1 scalar GAT + PWL layer-2 transform =======
__global__ void gat_l1_fused(const float* __restrict__ as2, const float* __restrict__ ad2, int N) {
    int node = (blockIdx.x * blockDim.x + threadIdx.x) >> 5;
    int lane = threadIdx.x & 31;
    if (node >= N) return;
    int off = node * SLOT;
    int deg = g_cursor[node];
    float dn = g_d1[node];
    float2 self = g_sx1[node];

    float dsum = 0.f, zacc = 0.f;
    for (int j = lane; j < deg; j += 32) {
        int sv = g_csr[off + j];
        float2 t = g_sx1[sv];
        float ex = exp2f(leaky(t.x + dn));
        dsum += ex;
        zacc += ex * t.y;
    }
#pragma unroll
    for (int o = 16; o; o >>= 1) {
        dsum += __shfl_xor_sync(0xffffffffu, dsum, o);
        zacc += __shfl_xor_sync(0xffffffffu, zacc, o);
    }
    float exs = exp2f(leaky(self.x + dn));
    float z = (zacc + exs * self.y) / (dsum + exs);

    // PWL segment m = #knees < z (search range [0,64])
    int m = 0;
#pragma unroll
    for (int s = 64; s; s >>= 1) {
        int t = m + s;
        if (t <= 64 && g_knee[t - 1] < z) m = t;
    }
    float2 A = ((const float2*)g_tabA)[m * 32 + lane];
    float2 C = ((const float2*)g_tabC)[m * 32 + lane];
    float o0 = A.x * z + C.x;
    float o1 = A.y * z + C.y;

    g_h2h[node * 32 + lane] = __floats2half2_rn(o0, o1);
    float2 a_s = ((const float2*)as2)[lane];
    float2 a_d = ((const float2*)ad2)[lane];
    float ps = o0 * a_s.x + o1 * a_s.y;
    float pd = o0 * a_d.x + o1 * a_d.y;
#pragma unroll
    for (int o = 16; o; o >>= 1) {
        ps += __shfl_down_sync(0xffffffffu, ps, o);
        pd += __shfl_down_sync(0xffffffffu, pd, o);
    }
    if (lane == 0) { g_s2[node] = ps * LOG2E; g_d2[node] = pd * LOG2E; }
}

// ======= K3: layer-2 wide GAT (fp16 gather, software-pipelined rounds) + layer-3 projection =======
__global__ void gat_l2(const float* __restrict__ b2, const float* __restrict__ W3,
                       const float* __restrict__ as3, const float* __restrict__ ad3, int N) {
    int node = (blockIdx.x * blockDim.x + threadIdx.x) >> 5;
    int lane = threadIdx.x & 31;
    if (node >= N) return;
    int off = node * SLOT;
    int deg = g_cursor[node];
    float dn = g_d2[node];

    float exs = exp2f(leaky(g_s2[node] + dn));
    float2 hself = __half22float2(g_h2h[node * 32 + lane]);
    float a0 = exs * hself.x;
    float a1 = exs * hself.y;
    float dsum = 0.f;

    // prologue: load round 0's edge + logit
    int sv = 0;
    float exv = 0.f;
    if (lane < deg) {
        sv = g_csr[off + lane];
        exv = exp2f(leaky(g_s2[sv] + dn));
    }
    for (int r = 0; r < deg; r += 32) {
        // prefetch round r+32 while broadcasting round r
        int jn = r + 32 + lane;
        int svn = 0;
        float exvn = 0.f;
        if (jn < deg) {
            svn = g_csr[off + jn];
            exvn = exp2f(leaky(g_s2[svn] + dn));
        }
        dsum += exv;
        int cnt = min(32, deg - r);
        if (cnt == 32) {
#pragma unroll 8
            for (int k = 0; k < 32; k++) {
                int sj = __shfl_sync(0xffffffffu, sv, k);
                float exj = __shfl_sync(0xffffffffu, exv, k);
                float2 hv = __half22float2(g_h2h[sj * 32 + lane]);
                a0 += exj * hv.x;
                a1 += exj * hv.y;
            }
        } else {
            for (int k = 0; k < cnt; k++) {
                int sj = __shfl_sync(0xffffffffu, sv, k);
                float exj = __shfl_sync(0xffffffffu, exv, k);
                float2 hv = __half22float2(g_h2h[sj * 32 + lane]);
                a0 += exj * hv.x;
                a1 += exj * hv.y;
            }
        }
        sv = svn;
        exv = exvn;
    }
#pragma unroll
    for (int o = 16; o; o >>= 1) dsum += __shfl_xor_sync(0xffffffffu, dsum, o);
    float inv = 1.f / (exs + dsum);
    float2 bb = ((const float2*)b2)[lane];
    float2 w3 = ((const float2*)W3)[lane];
    float x30 = fmaxf(a0 * inv + bb.x, 0.f);
    float x31 = fmaxf(a1 * inv + bb.y, 0.f);
    float p = x30 * w3.x + x31 * w3.y;
#pragma unroll
    for (int o = 16; o; o >>= 1) p += __shfl_down_sync(0xffffffffu, p, o);
    if (lane == 0) {
        g_sh3[node] = make_float2(p * as3[0] * LOG2E, p);
        g_d3[node] = p * ad3[0] * LOG2E;
    }
}

// ======= K4: layer-3 scalar GAT -> output; resets cursor invariant =======
__global__ void gat_out(const float* __restrict__ b3, float* __restrict__ out, int N) {
    int node = (blockIdx.x * blockDim.x + threadIdx.x) >> 5;
    int lane = threadIdx.x & 31;
    if (node >= N) return;
    int off = node * SLOT;
    int deg = g_cursor[node];
    float dn = g_d3[node];
    float2 self = g_sh3[node];

    float dsum = 0.f, acc = 0.f;
    for (int j = lane; j < deg; j += 32) {
        int sv = g_csr[off + j];
        float2 t = g_sh3[sv];
        float ex = exp2f(leaky(t.x + dn));
        dsum += ex;
        acc += ex * t.y;
    }
#pragma unroll
    for (int o = 16; o; o >>= 1) {
        dsum += __shfl_xor_sync(0xffffffffu, dsum, o);
        acc += __shfl_xor_sync(0xffffffffu, acc, o);
    }
    if (lane == 0) {
        float exs = exp2f(leaky(self.x + dn));
        out[node] = (acc + exs * self.y) / (dsum + exs) + b3[0];
        g_cursor[node] = 0;   // restore invariant for next call
    }
}

extern "C" void kernel_launch(void* const* d_in, const int* in_sizes, int n_in,
                              void* d_out, int out_size) {
    const float* x   = (const float*)d_in[0];
    const int*   ei  = (const int*)d_in[1];
    const float* W1  = (const float*)d_in[3];
    const float* as1 = (const float*)d_in[4];
    const float* ad1 = (const float*)d_in[5];
    const float* b1  = (const float*)d_in[6];
    const float* W2  = (const float*)d_in[7];
    const float* as2 = (const float*)d_in[8];
    const float* ad2 = (const float*)d_in[9];
    const float* b2  = (const float*)d_in[10];
    const float* W3  = (const float*)d_in[11];
    const float* as3 = (const float*)d_in[12];
    const float* ad3 = (const float*)d_in[13];
    const float* b3  = (const float*)d_in[14];

    int N = in_sizes[0];
    int E = in_sizes[1] / 2;
    const int* src = ei;
    const int* dst = ei + E;

    const int TB = 256;
    int gN32 = (N * 32 + TB - 1) / TB;
    int e4   = (E + 3) / 4;
    int gPS  = (((e4 > N) ? e4 : N) + TB - 1) / TB;

    prep_scatter<<<gPS, TB>>>(x, W1, as1, ad1, b1, W2, src, dst, N, E);
    gat_l1_fused<<<gN32, TB>>>(as2, ad2, N);
    gat_l2<<<gN32, TB>>>(b2, W3, as3, ad3, N);
    gat_out<<<gN32, TB>>>(b3, (float*)d_out, N);
}

// round 16
// speedup vs baseline: 1.1326x; 1.0370x over previous
#include <cuda_runtime.h>
#include <cuda_fp16.h>

#define MAXN 50176
#define SLOT 128
#define LOG2E 1.4426950408889634f

// Scratch (__device__ globals; no allocation allowed)
__device__ __align__(256) __half2 g_h2h[MAXN * 32];  // layer-2 features fp16 packed (feats 2k,2k+1 at slot k)
__device__ __align__(16) float2 g_sx1[MAXN];         // packed (s1, x)
__device__ __align__(16) float2 g_sh3[MAXN];         // packed (s3, h3)
__device__ float g_d1[MAXN];
__device__ float g_s2[MAXN], g_d2[MAXN];
__device__ float g_d3[MAXN];
__device__ int g_cursor[MAXN];       // INVARIANT: zero at entry (zero-init at load; gat_out resets)
__device__ int g_csr[MAXN * SLOT];   // fixed-stride CSR
// piecewise-linear table for h2(z) = A_m * z + C_m, 65 segments x 64 features
__device__ __align__(16) float g_tabA[65 * 64];
__device__ __align__(16) float g_tabC[65 * 64];
__device__ float g_knee[64];

__device__ __forceinline__ float leaky(float v) { return v > 0.f ? v : 0.2f * v; }

// ======= K1: node prep (rank-1 layer-1 scalars) + CSR scatter + (block 0) PWL table build =======
__global__ void prep_scatter(const float* __restrict__ x, const float* __restrict__ W1,
                             const float* __restrict__ as1, const float* __restrict__ ad1,
                             const float* __restrict__ b1, const float* __restrict__ W2,
                             const int* __restrict__ src, const int* __restrict__ dst,
                             int N, int E) {
    __shared__ float cs_sh, cd_sh;
    int base = blockIdx.x * blockDim.x;
    if (base < N && threadIdx.x == 0) {
        float cs = 0.f, cd = 0.f;
#pragma unroll
        for (int j = 0; j < 64; j++) { cs += W1[j] * as1[j]; cd += W1[j] * ad1[j]; }
        cs_sh = cs; cd_sh = cd;
    }
    if (base < N) __syncthreads();

    // ---- block 0: build the piecewise-linear (A,C) table ----
    if (blockIdx.x == 0) {
        __shared__ float rk[64], rw[64], rb[64];
        __shared__ float sk[64], sw[64], sb[64];
        __shared__ int sidx[64];
        int t = threadIdx.x;
        if (t < 64) {
            float w = W1[t], b = b1[t];
            float knee = (w != 0.f) ? (-b / w) : __int_as_float(0x7f800000);
            rk[t] = knee; rw[t] = w; rb[t] = b;
        }
        __syncthreads();
        if (t < 64) {
            float knee = rk[t];
            int rank = 0;
            for (int j = 0; j < 64; j++)
                rank += (rk[j] < knee) || (rk[j] == knee && j < t);
            float w = rw[t], b = rb[t];
            float sgn = (w > 0.f) ? 1.f : ((w < 0.f) ? -1.f : 0.f);
            sk[rank] = knee; sw[rank] = sgn * w; sb[rank] = sgn * b; sidx[rank] = t;
        }
        __syncthreads();
        if (t < 64) {
            g_knee[t] = sk[t];
            float A = 0.f, C = 0.f;
            for (int j = 0; j < 64; j++) {
                float w = rw[j], b = rb[j];
                bool act = (w < 0.f) || (w == 0.f && b > 0.f);
                if (act) {
                    float w2v = W2[j * 64 + t];
                    A += w * w2v; C += b * w2v;
                }
            }
            g_tabA[t] = A; g_tabC[t] = C;
            for (int m = 1; m <= 64; m++) {
                int j = sidx[m - 1];
                float w2v = W2[j * 64 + t];
                A += sw[m - 1] * w2v; C += sb[m - 1] * w2v;
                g_tabA[m * 64 + t] = A; g_tabC[m * 64 + t] = C;
            }
        }
    }

    // ---- edge work: 4 edges/thread, cursor-ATOMG CSR scatter ----
    int t = base + threadIdx.x;
    int e0 = t * 4;
    if (e0 + 3 < E) {
        int4 s4 = ((const int4*)src)[t];
        int4 d4 = ((const int4*)dst)[t];
        int r0 = atomicAdd(&g_cursor[d4.x], 1);
        int r1 = atomicAdd(&g_cursor[d4.y], 1);
        int r2 = atomicAdd(&g_cursor[d4.z], 1);
        int r3 = atomicAdd(&g_cursor[d4.w], 1);
        g_csr[d4.x * SLOT + r0] = s4.x;
        g_csr[d4.y * SLOT + r1] = s4.y;
        g_csr[d4.z * SLOT + r2] = s4.z;
        g_csr[d4.w * SLOT + r3] = s4.w;
    } else if (e0 < E) {
        for (int e = e0; e < E; e++) {
            int d = dst[e];
            int r = atomicAdd(&g_cursor[d], 1);
            g_csr[d * SLOT + r] = src[e];
        }
    }
    if (t < N) {
        float xv = x[t];
        g_sx1[t] = make_float2(xv * cs_sh, xv);
        g_d1[t] = xv * cd_sh;
    }
}

// ======= K2: layer-1 scalar GAT + PWL layer-2 transform (identical to R12) =======
__global__ void gat_l1_fused(const float* __restrict__ as2, const float* __restrict__ ad2, int N) {
    int node = (blockIdx.x * blockDim.x + threadIdx.x) >> 5;
    int lane = threadIdx.x & 31;
    if (node >= N) return;
    int off = node * SLOT;
    int deg = g_cursor[node];
    float dn = g_d1[node];
    float2 self = g_sx1[node];

    float dsum = 0.f, zacc = 0.f;
    for (int j = lane; j < deg; j += 32) {
        int sv = g_csr[off + j];
        float2 t = g_sx1[sv];
        float ex = exp2f(leaky(t.x + dn) * LOG2E);
        dsum += ex;
        zacc += ex * t.y;
    }
#pragma unroll
    for (int o = 16; o; o >>= 1) {
        dsum += __shfl_xor_sync(0xffffffffu, dsum, o);
        zacc += __shfl_xor_sync(0xffffffffu, zacc, o);
    }
    float exs = exp2f(leaky(self.x + dn) * LOG2E);
    float z = (zacc + exs * self.y) / (dsum + exs);

    int m = 0;
#pragma unroll
    for (int s = 64; s; s >>= 1) {
        int t = m + s;
        if (t <= 64 && g_knee[t - 1] < z) m = t;
    }
    float2 A = ((const float2*)g_tabA)[m * 32 + lane];
    float2 C = ((const float2*)g_tabC)[m * 32 + lane];
    float o0 = A.x * z + C.x;
    float o1 = A.y * z + C.y;

    g_h2h[node * 32 + lane] = __floats2half2_rn(o0, o1);
    float2 a_s = ((const float2*)as2)[lane];
    float2 a_d = ((const float2*)ad2)[lane];
    float ps = o0 * a_s.x + o1 * a_s.y;
    float pd = o0 * a_d.x + o1 * a_d.y;
#pragma unroll
    for (int o = 16; o; o >>= 1) {
        ps += __shfl_down_sync(0xffffffffu, ps, o);
        pd += __shfl_down_sync(0xffffffffu, pd, o);
    }
    if (lane == 0) { g_s2[node] = ps; g_d2[node] = pd; }
}

// ======= K3: layer-2 wide GAT — paired-edge LDG.64 gathers + layer-3 projection =======
__global__ void gat_l2(const float* __restrict__ b2, const float* __restrict__ W3,
                       const float* __restrict__ as3, const float* __restrict__ ad3, int N) {
    int node = (blockIdx.x * blockDim.x + threadIdx.x) >> 5;
    int lane = threadIdx.x & 31;
    int p = lane & 15;        // feature group: feats 4p..4p+3
    int h = lane >> 4;        // half-warp id: handles edge k+h in each pair
    if (node >= N) return;
    int off = node * SLOT;
    int deg = g_cursor[node];
    float dn = g_d2[node];

    float exs = exp2f(leaky(g_s2[node] + dn) * LOG2E);
    // init accumulators from self row (h==0 half only, to avoid double count)
    float a0 = 0.f, a1 = 0.f, a2 = 0.f, a3 = 0.f;
    {
        uint2 u = ((const uint2*)g_h2h)[node * 16 + p];
        float2 f0 = __half22float2(*(const __half2*)&u.x);
        float2 f1 = __half22float2(*(const __half2*)&u.y);
        if (h == 0) {
            a0 = exs * f0.x; a1 = exs * f0.y;
            a2 = exs * f1.x; a3 = exs * f1.y;
        }
    }
    float dsum = 0.f;
    for (int r = 0; r < deg; r += 32) {
        int j = r + lane;
        int sv = 0;
        float exv = 0.f;
        if (j < deg) {
            sv = g_csr[off + j];
            exv = exp2f(leaky(g_s2[sv] + dn) * LOG2E);
        }
        dsum += exv;
        int cnt = min(32, deg - r);
        // paired broadcast: iteration m covers edges m (h=0) and m+1 (h=1).
        // lanes whose edge kk >= cnt carry exv=0/sv=0 from the predication above -> +0.
#pragma unroll 4
        for (int m = 0; m < cnt; m += 2) {
            int kk = m + h;
            int sj = __shfl_sync(0xffffffffu, sv, kk);
            float exj = __shfl_sync(0xffffffffu, exv, kk);
            uint2 u = ((const uint2*)g_h2h)[sj * 16 + p];
            float2 f0 = __half22float2(*(const __half2*)&u.x);
            float2 f1 = __half22float2(*(const __half2*)&u.y);
            a0 += exj * f0.x; a1 += exj * f0.y;
            a2 += exj * f1.x; a3 += exj * f1.y;
        }
    }
#pragma unroll
    for (int o = 16; o; o >>= 1) dsum += __shfl_xor_sync(0xffffffffu, dsum, o);
    // combine the two half-warp accumulators (lane L and L^16 cover same feats)
    a0 += __shfl_xor_sync(0xffffffffu, a0, 16);
    a1 += __shfl_xor_sync(0xffffffffu, a1, 16);
    a2 += __shfl_xor_sync(0xffffffffu, a2, 16);
    a3 += __shfl_xor_sync(0xffffffffu, a3, 16);

    float inv = 1.f / (exs + dsum);
    float4 bb = ((const float4*)b2)[p];
    float4 w3 = ((const float4*)W3)[p];
    float x0 = fmaxf(a0 * inv + bb.x, 0.f);
    float x1 = fmaxf(a1 * inv + bb.y, 0.f);
    float x2 = fmaxf(a2 * inv + bb.z, 0.f);
    float x3 = fmaxf(a3 * inv + bb.w, 0.f);
    float pdot = x0 * w3.x + x1 * w3.y + x2 * w3.z + x3 * w3.w;
    // sum over the 16 feature groups (each half-warp independently holds the full sum)
#pragma unroll
    for (int o = 8; o; o >>= 1) pdot += __shfl_xor_sync(0xffffffffu, pdot, o);
    if (lane == 0) {
        g_sh3[node] = make_float2(pdot * as3[0], pdot);
        g_d3[node] = pdot * ad3[0];
    }
}

// ======= K4: layer-3 scalar GAT -> output; resets cursor invariant (identical to R12) =======
__global__ void gat_out(const float* __restrict__ b3, float* __restrict__ out, int N) {
    int node = (blockIdx.x * blockDim.x + threadIdx.x) >> 5;
    int lane = threadIdx.x & 31;
    if (node >= N) return;
    int off = node * SLOT;
    int deg = g_cursor[node];
    float dn = g_d3[node];
    float2 self = g_sh3[node];

    float dsum = 0.f, acc = 0.f;
    for (int j = lane; j < deg; j += 32) {
        int sv = g_csr[off + j];
        float2 t = g_sh3[sv];
        float ex = exp2f(leaky(t.x + dn) * LOG2E);
        dsum += ex;
        acc += ex * t.y;
    }
#pragma unroll
    for (int o = 16; o; o >>= 1) {
        dsum += __shfl_xor_sync(0xffffffffu, dsum, o);
        acc += __shfl_xor_sync(0xffffffffu, acc, o);
    }
    if (lane == 0) {
        float exs = exp2f(leaky(self.x + dn) * LOG2E);
        out[node] = (acc + exs * self.y) / (dsum + exs) + b3[0];
        g_cursor[node] = 0;   // restore invariant for next call
    }
}

extern "C" void kernel_launch(void* const* d_in, const int* in_sizes, int n_in,
                              void* d_out, int out_size) {
    const float* x   = (const float*)d_in[0];
    const int*   ei  = (const int*)d_in[1];
    const float* W1  = (const float*)d_in[3];
    const float* as1 = (const float*)d_in[4];
    const float* ad1 = (const float*)d_in[5];
    const float* b1  = (const float*)d_in[6];
    const float* W2  = (const float*)d_in[7];
    const float* as2 = (const float*)d_in[8];
    const float* ad2 = (const float*)d_in[9];
    const float* b2  = (const float*)d_in[10];
    const float* W3  = (const float*)d_in[11];
    const float* as3 = (const float*)d_in[12];
    const float* ad3 = (const float*)d_in[13];
    const float* b3  = (const float*)d_in[14];

    int N = in_sizes[0];
    int E = in_sizes[1] / 2;
    const int* src = ei;
    const int* dst = ei + E;

    const int TB = 256;
    int gN32 = (N * 32 + TB - 1) / TB;
    int e4   = (E + 3) / 4;
    int gPS  = (((e4 > N) ? e4 : N) + TB - 1) / TB;

    prep_scatter<<<gPS, TB>>>(x, W1, as1, ad1, b1, W2, src, dst, N, E);
    gat_l1_fused<<<gN32, TB>>>(as2, ad2, N);
    gat_l2<<<gN32, TB>>>(b2, W3, as3, ad3, N);
    gat_out<<<gN32, TB>>>(b3, (float*)d_out, N);
}